// round 2
// baseline (speedup 1.0000x reference)
#include <cuda_runtime.h>
#include <math.h>

// ---------------------------------------------------------------------------
// K[i,j] = | prod_k cos((x_ik - y_jk)/2) |
//        = | Px_i * Py_j * prod_k (1 + tan(x_ik/2) * tan(y_jk/2)) |
// where Px_i = prod_k cos(x_ik/2), Py_j = prod_k cos(y_jk/2).
// Phase 1: per-row sincos -> tan tables (transposed) + row cos-products.
// Phase 2: 64x128 tile, 4x8 per thread, packed f32x2: 2 ops per k per pair.
// ---------------------------------------------------------------------------

#define MAXROWS 16384
#define MAXD 64

__device__ float g_Tx[MAXD * MAXROWS];
__device__ float g_Ty[MAXD * MAXROWS];
__device__ float g_Px[MAXROWS];
__device__ float g_Py[MAXROWS];

typedef unsigned long long ull;

// --- packed f32x2 helpers (sm_103a only; ptxas never auto-fuses) -----------
__device__ __forceinline__ ull f2_mul(ull a, ull b) {
    ull r; asm("mul.rn.f32x2 %0, %1, %2;" : "=l"(r) : "l"(a), "l"(b)); return r;
}
__device__ __forceinline__ ull f2_fma(ull a, ull b, ull c) {
    ull r; asm("fma.rn.f32x2 %0, %1, %2, %3;" : "=l"(r) : "l"(a), "l"(b), "l"(c)); return r;
}
__device__ __forceinline__ ull f2_pack(float lo, float hi) {
    ull r;
    asm("mov.b64 %0, {%1, %2};" : "=l"(r) : "r"(__float_as_uint(lo)), "r"(__float_as_uint(hi)));
    return r;
}
__device__ __forceinline__ void f2_unpack(ull v, float& lo, float& hi) {
    unsigned int a, b;
    asm("mov.b64 {%0, %1}, %2;" : "=r"(a), "=r"(b) : "l"(v));
    lo = __uint_as_float(a); hi = __uint_as_float(b);
}

// --- Phase 1: one thread per row ------------------------------------------
__global__ void qk_pre(const float* __restrict__ x, const float* __restrict__ y,
                       int n, int m, int d) {
    int i = blockIdx.x * blockDim.x + threadIdx.x;
    if (i >= n + m) return;
    if (i < n) {
        float p = 1.0f;
        for (int k = 0; k < d; k++) {
            float s, c;
            sincosf(0.5f * x[i * d + k], &s, &c);
            if (c == 0.0f) c = 1e-30f;  // unreachable for finite fp32 inputs; belt+braces
            p *= c;
            g_Tx[k * n + i] = s / c;
        }
        g_Px[i] = p;
    } else {
        int j = i - n;
        float p = 1.0f;
        for (int k = 0; k < d; k++) {
            float s, c;
            sincosf(0.5f * y[j * d + k], &s, &c);
            if (c == 0.0f) c = 1e-30f;
            p *= c;
            g_Ty[k * m + j] = s / c;
        }
        g_Py[j] = p;
    }
}

// --- Phase 2: 64 rows x 128 cols per CTA, 256 threads, 4x8 per thread ------
template <int D>
__global__ __launch_bounds__(256) void qk_tile(float* __restrict__ out,
                                               int n, int m) {
    // X-side duplicated: one LDS.128 yields {xi,xi,xi+1,xi+1} = two broadcast
    // f32x2 operands. Y-side planar: one LDS.128 = two packed col-pairs.
    __shared__ __align__(16) float sTx[D][128];   // 64 rows duplicated
    __shared__ __align__(16) float sTy[D][128];   // 128 cols planar
    __shared__ __align__(16) float sPx[64];
    __shared__ __align__(16) float sPy[128];

    const int tid = threadIdx.x;
    const int bm0 = blockIdx.y * 64;
    const int bn0 = blockIdx.x * 128;

    for (int idx = tid; idx < D * 64; idx += 256) {
        int k = idx >> 6, r = idx & 63;
        int gi = bm0 + r; if (gi >= n) gi = n - 1;
        float v = g_Tx[k * n + gi];
        *reinterpret_cast<float2*>(&sTx[k][2 * r]) = make_float2(v, v);
    }
    for (int idx = tid; idx < D * 128; idx += 256) {
        int k = idx >> 7, r = idx & 127;
        int gj = bn0 + r; if (gj >= m) gj = m - 1;
        sTy[k][r] = g_Ty[k * m + gj];
    }
    if (tid < 64) { int gi = bm0 + tid; if (gi >= n) gi = n - 1; sPx[tid] = g_Px[gi]; }
    if (tid < 128) { int gj = bn0 + tid; if (gj >= m) gj = m - 1; sPy[tid] = g_Py[gj]; }
    __syncthreads();

    const int tx = tid & 15;    // col group -> cols j0..j0+7
    const int ty = tid >> 4;    // row group -> rows i0..i0+3
    const int i0 = ty * 4;
    const int j0 = tx * 8;

    const ull ONE2 = f2_pack(1.0f, 1.0f);
    ull acc[4][4];
#pragma unroll
    for (int ii = 0; ii < 4; ii++)
#pragma unroll
        for (int jj = 0; jj < 4; jj++) acc[ii][jj] = ONE2;

#pragma unroll
    for (int k = 0; k < D; k++) {
        // 2x LDS.128 each side
        ulonglong2 ya = *reinterpret_cast<const ulonglong2*>(&sTy[k][j0]);
        ulonglong2 yb = *reinterpret_cast<const ulonglong2*>(&sTy[k][j0 + 4]);
        ulonglong2 xa = *reinterpret_cast<const ulonglong2*>(&sTx[k][2 * i0]);
        ulonglong2 xb = *reinterpret_cast<const ulonglong2*>(&sTx[k][2 * i0 + 4]);
        ull xp[4] = {xa.x, xa.y, xb.x, xb.y};
        ull yp[4] = {ya.x, ya.y, yb.x, yb.y};
#pragma unroll
        for (int ii = 0; ii < 4; ii++) {
#pragma unroll
            for (int jj = 0; jj < 4; jj++) {
                // acc *= (1 + tx*ty)  ->  acc += (acc*tx)*ty
                ull u = f2_mul(acc[ii][jj], xp[ii]);
                acc[ii][jj] = f2_fma(u, yp[jj], acc[ii][jj]);
            }
        }
    }

    // epilogue: scale by Px*Py, abs, store
    ulonglong2 pya = *reinterpret_cast<const ulonglong2*>(&sPy[j0]);
    ulonglong2 pyb = *reinterpret_cast<const ulonglong2*>(&sPy[j0 + 4]);
    ull pyp[4] = {pya.x, pya.y, pyb.x, pyb.y};

    const bool interior = (bm0 + 63 < n) && (bn0 + 127 < m) && ((m & 3) == 0);
#pragma unroll
    for (int ii = 0; ii < 4; ii++) {
        float px = sPx[i0 + ii];
        ull pxp = f2_pack(px, px);
        float v[8];
#pragma unroll
        for (int jj = 0; jj < 4; jj++) {
            ull r = f2_mul(acc[ii][jj], pyp[jj]);
            r = f2_mul(r, pxp);
            float lo, hi;
            f2_unpack(r, lo, hi);
            v[2 * jj] = fabsf(lo);
            v[2 * jj + 1] = fabsf(hi);
        }
        int gi = bm0 + i0 + ii;
        int gj = bn0 + j0;
        if (interior) {
            *reinterpret_cast<float4*>(&out[(long long)gi * m + gj]) =
                make_float4(v[0], v[1], v[2], v[3]);
            *reinterpret_cast<float4*>(&out[(long long)gi * m + gj + 4]) =
                make_float4(v[4], v[5], v[6], v[7]);
        } else if (gi < n) {
#pragma unroll
            for (int q = 0; q < 8; q++)
                if (gj + q < m) out[(long long)gi * m + gj + q] = v[q];
        }
    }
}

// --- generic fallback (runtime d) ------------------------------------------
__global__ void qk_generic(float* __restrict__ out, int n, int m, int d) {
    int j = blockIdx.x * blockDim.x + threadIdx.x;
    int i = blockIdx.y;
    if (j >= m || i >= n) return;
    float p = 1.0f;
    for (int k = 0; k < d; k++)
        p = fmaf(p * g_Tx[k * n + i], g_Ty[k * m + j], p);
    out[(long long)i * m + j] = fabsf(p * g_Px[i] * g_Py[j]);
}

extern "C" void kernel_launch(void* const* d_in, const int* in_sizes, int n_in,
                              void* d_out, int out_size) {
    const float* x = (const float*)d_in[0];
    const float* y = (const float*)d_in[1];
    float* out = (float*)d_out;

    long long s0 = in_sizes[0], s1 = in_sizes[1];
    int d = (int)(0.5 + sqrt((double)s0 * (double)s1 / (double)out_size));
    if (d < 1) d = 1;
    int n = (int)(s0 / d);
    int m = (int)(s1 / d);

    {
        int total = n + m;
        int threads = 256;
        qk_pre<<<(total + threads - 1) / threads, threads>>>(x, y, n, m, d);
    }

    if (d == 16) {
        dim3 grid((m + 127) / 128, (n + 63) / 64);
        qk_tile<16><<<grid, 256>>>(out, n, m);
    } else {
        dim3 grid((m + 255) / 256, n);
        qk_generic<<<grid, 256>>>(out, n, m, d);
    }
}

// round 3
// speedup vs baseline: 1.1963x; 1.1963x over previous
#include <cuda_runtime.h>
#include <math.h>

// ---------------------------------------------------------------------------
// K[i,j] = | prod_k cos((x_ik - y_jk)/2) |
//        = | Px_i * Py_j * prod_k (1 + tan(x_ik/2)*tan(y_jk/2)) |
// Phase 1: tan tables (transposed) + per-row cos products.
// Phase 2: 64x64 tile, 256 thr, 4x4 f32x2 per thread, 2 packed ops per k.
// ---------------------------------------------------------------------------

#define MAXROWS 16384
#define MAXD 64

__device__ float g_Tx[MAXD * MAXROWS];
__device__ float g_Ty[MAXD * MAXROWS];
__device__ float g_Px[MAXROWS];
__device__ float g_Py[MAXROWS];

typedef unsigned long long ull;

__device__ __forceinline__ ull f2_mul(ull a, ull b) {
    ull r; asm("mul.rn.f32x2 %0, %1, %2;" : "=l"(r) : "l"(a), "l"(b)); return r;
}
__device__ __forceinline__ ull f2_fma(ull a, ull b, ull c) {
    ull r; asm("fma.rn.f32x2 %0, %1, %2, %3;" : "=l"(r) : "l"(a), "l"(b), "l"(c)); return r;
}
__device__ __forceinline__ ull f2_pack(float lo, float hi) {
    ull r;
    asm("mov.b64 %0, {%1, %2};" : "=l"(r) : "r"(__float_as_uint(lo)), "r"(__float_as_uint(hi)));
    return r;
}
__device__ __forceinline__ void f2_unpack(ull v, float& lo, float& hi) {
    unsigned int a, b;
    asm("mov.b64 {%0, %1}, %2;" : "=r"(a), "=r"(b) : "l"(v));
    lo = __uint_as_float(a); hi = __uint_as_float(b);
}

// --- Phase 1: one thread per row ------------------------------------------
__global__ void qk_pre(const float* __restrict__ x, const float* __restrict__ y,
                       int n, int m, int d) {
    int i = blockIdx.x * blockDim.x + threadIdx.x;
    if (i >= n + m) return;
    if (i < n) {
        float p = 1.0f;
        for (int k = 0; k < d; k++) {
            float s, c;
            sincosf(0.5f * x[i * d + k], &s, &c);
            if (c == 0.0f) c = 1e-30f;
            p *= c;
            g_Tx[k * n + i] = s / c;
        }
        g_Px[i] = p;
    } else {
        int j = i - n;
        float p = 1.0f;
        for (int k = 0; k < d; k++) {
            float s, c;
            sincosf(0.5f * y[j * d + k], &s, &c);
            if (c == 0.0f) c = 1e-30f;
            p *= c;
            g_Ty[k * m + j] = s / c;
        }
        g_Py[j] = p;
    }
}

// --- Phase 2: 64x64 tile, 256 threads, 4 rows x 4 cols per thread ----------
template <int D>
__global__ __launch_bounds__(256, 5) void qk_tile(float* __restrict__ out,
                                                  int n, int m) {
    // X-side duplicated ({v,v} pairs): LDS.128 -> 2 ready broadcast operands.
    // Y-side planar: LDS.128 -> 2 packed col-pairs.
    __shared__ __align__(16) float sTx[D][128];  // 64 rows duplicated
    __shared__ __align__(16) float sTy[D][64];   // 64 cols planar
    __shared__ __align__(16) float sPx[64];
    __shared__ __align__(16) float sPy[64];

    const int tid = threadIdx.x;
    const int bm0 = blockIdx.y * 64;
    const int bn0 = blockIdx.x * 64;

    for (int idx = tid; idx < D * 64; idx += 256) {
        int k = idx >> 6, r = idx & 63;
        int gi = bm0 + r; if (gi >= n) gi = n - 1;
        float v = g_Tx[k * n + gi];
        *reinterpret_cast<float2*>(&sTx[k][2 * r]) = make_float2(v, v);
        int gj = bn0 + r; if (gj >= m) gj = m - 1;
        sTy[k][r] = g_Ty[k * m + gj];
    }
    if (tid < 64) {
        int gi = bm0 + tid; if (gi >= n) gi = n - 1;
        sPx[tid] = g_Px[gi];
        int gj = bn0 + tid; if (gj >= m) gj = m - 1;
        sPy[tid] = g_Py[gj];
    }
    __syncthreads();

    const int tx = tid & 15;   // col group: cols j0..j0+3
    const int ty = tid >> 4;   // row group: rows i0..i0+3
    const int i0 = ty * 4;
    const int j0 = tx * 4;

    const ull ONE2 = f2_pack(1.0f, 1.0f);
    ull a00 = ONE2, a01 = ONE2, a10 = ONE2, a11 = ONE2;
    ull a20 = ONE2, a21 = ONE2, a30 = ONE2, a31 = ONE2;

#pragma unroll
    for (int k = 0; k < D; k++) {
        // 1x LDS.128 y, 2x LDS.128 x (all scalar ulls, no indexed arrays)
        ulonglong2 yv = *reinterpret_cast<const ulonglong2*>(&sTy[k][j0]);
        ulonglong2 xa = *reinterpret_cast<const ulonglong2*>(&sTx[k][2 * i0]);
        ulonglong2 xb = *reinterpret_cast<const ulonglong2*>(&sTx[k][2 * i0 + 4]);
        // acc *= (1 + tx*ty)  ->  acc = fma(acc*tx, ty, acc)
        a00 = f2_fma(f2_mul(a00, xa.x), yv.x, a00);
        a01 = f2_fma(f2_mul(a01, xa.x), yv.y, a01);
        a10 = f2_fma(f2_mul(a10, xa.y), yv.x, a10);
        a11 = f2_fma(f2_mul(a11, xa.y), yv.y, a11);
        a20 = f2_fma(f2_mul(a20, xb.x), yv.x, a20);
        a21 = f2_fma(f2_mul(a21, xb.x), yv.y, a21);
        a30 = f2_fma(f2_mul(a30, xb.y), yv.x, a30);
        a31 = f2_fma(f2_mul(a31, xb.y), yv.y, a31);
    }

    // epilogue: scale by Px*Py, abs, store
    ulonglong2 pyv = *reinterpret_cast<const ulonglong2*>(&sPy[j0]);
    const bool interior = (bm0 + 63 < n) && (bn0 + 63 < m) && ((m & 3) == 0);

    ull r0[4] = {a00, a10, a20, a30};
    ull r1[4] = {a01, a11, a21, a31};
#pragma unroll
    for (int ii = 0; ii < 4; ii++) {
        float px = sPx[i0 + ii];
        ull pxp = f2_pack(px, px);
        ull v0 = f2_mul(f2_mul(r0[ii], pyv.x), pxp);
        ull v1 = f2_mul(f2_mul(r1[ii], pyv.y), pxp);
        float e0, e1, e2, e3;
        f2_unpack(v0, e0, e1);
        f2_unpack(v1, e2, e3);
        e0 = fabsf(e0); e1 = fabsf(e1); e2 = fabsf(e2); e3 = fabsf(e3);
        int gi = bm0 + i0 + ii;
        int gj = bn0 + j0;
        if (interior) {
            *reinterpret_cast<float4*>(&out[(long long)gi * m + gj]) =
                make_float4(e0, e1, e2, e3);
        } else if (gi < n) {
            if (gj + 0 < m) out[(long long)gi * m + gj + 0] = e0;
            if (gj + 1 < m) out[(long long)gi * m + gj + 1] = e1;
            if (gj + 2 < m) out[(long long)gi * m + gj + 2] = e2;
            if (gj + 3 < m) out[(long long)gi * m + gj + 3] = e3;
        }
    }
}

// --- generic fallback (runtime d) ------------------------------------------
__global__ void qk_generic(float* __restrict__ out, int n, int m, int d) {
    int j = blockIdx.x * blockDim.x + threadIdx.x;
    int i = blockIdx.y;
    if (j >= m || i >= n) return;
    float p = 1.0f;
    for (int k = 0; k < d; k++)
        p = fmaf(p * g_Tx[k * n + i], g_Ty[k * m + j], p);
    out[(long long)i * m + j] = fabsf(p * g_Px[i] * g_Py[j]);
}

extern "C" void kernel_launch(void* const* d_in, const int* in_sizes, int n_in,
                              void* d_out, int out_size) {
    const float* x = (const float*)d_in[0];
    const float* y = (const float*)d_in[1];
    float* out = (float*)d_out;

    long long s0 = in_sizes[0], s1 = in_sizes[1];
    int d = (int)(0.5 + sqrt((double)s0 * (double)s1 / (double)out_size));
    if (d < 1) d = 1;
    int n = (int)(s0 / d);
    int m = (int)(s1 / d);

    {
        int total = n + m;
        int threads = 256;
        qk_pre<<<(total + threads - 1) / threads, threads>>>(x, y, n, m, d);
    }

    if (d == 16) {
        dim3 grid((m + 63) / 64, (n + 63) / 64);
        qk_tile<16><<<grid, 256>>>(out, n, m);
    } else {
        dim3 grid((m + 255) / 256, n);
        qk_generic<<<grid, 256>>>(out, n, m, d);
    }
}